// round 3
// baseline (speedup 1.0000x reference)
#include <cuda_runtime.h>

#define S_LEN    1024
#define DM       2048
#define NUM_HEADS 256
#define HEAD_DIM  8
#define ATT_SCALE 0.35355339059327373f   // 1/sqrt(8)

// ---------------- scratch (static device globals; no allocation) ----------------
__device__ float g_q[S_LEN * DM];
__device__ float g_k[S_LEN * HEAD_DIM];
__device__ float g_v[S_LEN * HEAD_DIM];
__device__ float g_attn[S_LEN * DM];

// ---------------- SGEMM with bias: C[M,N] = A[M,K] @ B[K,N] + bias ----------------
// BM=128 BN=128 BK=16, 256 threads, 8x8 per thread.
#define BM 128
#define BN 128
#define BK 16

__global__ __launch_bounds__(256) void sgemm_bias(
    const float* __restrict__ A, const float* __restrict__ B,
    const float* __restrict__ bias, float* __restrict__ C,
    int M, int N, int K)
{
    __shared__ float As[BK][BM];
    __shared__ float Bs[BK][BN];

    const int tid = threadIdx.x;
    const int blockRow = blockIdx.y * BM;
    const int blockCol = blockIdx.x * BN;

    const int rowA = tid >> 2;          // 0..63
    const int colA = (tid & 3) * 4;     // 0,4,8,12
    const int rowB = tid >> 5;          // 0..7
    const int colB = (tid & 31) * 4;

    const int tr = (tid >> 4) * 8;
    const int tc = (tid & 15) * 8;

    float acc[8][8];
#pragma unroll
    for (int i = 0; i < 8; i++)
#pragma unroll
        for (int j = 0; j < 8; j++) acc[i][j] = 0.0f;

    for (int k0 = 0; k0 < K; k0 += BK) {
        // load A tile (transposed into As[k][m])
#pragma unroll
        for (int p = 0; p < 2; p++) {
            int r = rowA + p * 64;
            float4 a = *(const float4*)&A[(size_t)(blockRow + r) * K + k0 + colA];
            As[colA + 0][r] = a.x;
            As[colA + 1][r] = a.y;
            As[colA + 2][r] = a.z;
            As[colA + 3][r] = a.w;
        }
        // load B tile
#pragma unroll
        for (int p = 0; p < 2; p++) {
            int r = rowB + p * 8;
            *(float4*)&Bs[r][colB] =
                *(const float4*)&B[(size_t)(k0 + r) * N + blockCol + colB];
        }
        __syncthreads();

#pragma unroll
        for (int k = 0; k < BK; k++) {
            float am[8], bm[8];
            *(float4*)&am[0] = *(const float4*)&As[k][tr];
            *(float4*)&am[4] = *(const float4*)&As[k][tr + 4];
            *(float4*)&bm[0] = *(const float4*)&Bs[k][tc];
            *(float4*)&bm[4] = *(const float4*)&Bs[k][tc + 4];
#pragma unroll
            for (int i = 0; i < 8; i++)
#pragma unroll
                for (int j = 0; j < 8; j++)
                    acc[i][j] += am[i] * bm[j];
        }
        __syncthreads();
    }

    float bb[8];
#pragma unroll
    for (int j = 0; j < 8; j++) bb[j] = bias[blockCol + tc + j];

#pragma unroll
    for (int i = 0; i < 8; i++) {
        float4 r0, r1;
        r0.x = acc[i][0] + bb[0]; r0.y = acc[i][1] + bb[1];
        r0.z = acc[i][2] + bb[2]; r0.w = acc[i][3] + bb[3];
        r1.x = acc[i][4] + bb[4]; r1.y = acc[i][5] + bb[5];
        r1.z = acc[i][6] + bb[6]; r1.w = acc[i][7] + bb[7];
        float* cp = &C[(size_t)(blockRow + tr + i) * N + blockCol + tc];
        *(float4*)cp = r0;
        *(float4*)(cp + 4) = r1;
    }
}

// ---------------- K/V projection: k = x@Wk+bk, v = x@Wv+bv (N=8) ----------------
__global__ __launch_bounds__(128) void kv_kernel(
    const float* __restrict__ x,
    const float* __restrict__ Wk, const float* __restrict__ bk,
    const float* __restrict__ Wv, const float* __restrict__ bv,
    float* __restrict__ kout, float* __restrict__ vout)
{
    const int i = blockIdx.x;
    const int tid = threadIdx.x;
    float aK[8] = {0,0,0,0,0,0,0,0};
    float aV[8] = {0,0,0,0,0,0,0,0};
    const float* xr = x + (size_t)i * DM;

    for (int c = tid; c < DM; c += 128) {
        float xv = xr[c];
        float4 w0 = *(const float4*)(Wk + c * 8);
        float4 w1 = *(const float4*)(Wk + c * 8 + 4);
        aK[0] += xv * w0.x; aK[1] += xv * w0.y; aK[2] += xv * w0.z; aK[3] += xv * w0.w;
        aK[4] += xv * w1.x; aK[5] += xv * w1.y; aK[6] += xv * w1.z; aK[7] += xv * w1.w;
        float4 u0 = *(const float4*)(Wv + c * 8);
        float4 u1 = *(const float4*)(Wv + c * 8 + 4);
        aV[0] += xv * u0.x; aV[1] += xv * u0.y; aV[2] += xv * u0.z; aV[3] += xv * u0.w;
        aV[4] += xv * u1.x; aV[5] += xv * u1.y; aV[6] += xv * u1.z; aV[7] += xv * u1.w;
    }

#pragma unroll
    for (int d = 0; d < 8; d++) {
#pragma unroll
        for (int o = 16; o > 0; o >>= 1) {
            aK[d] += __shfl_xor_sync(0xffffffffu, aK[d], o);
            aV[d] += __shfl_xor_sync(0xffffffffu, aV[d], o);
        }
    }

    __shared__ float red[4][16];
    const int warp = tid >> 5, lane = tid & 31;
    if (lane == 0) {
#pragma unroll
        for (int d = 0; d < 8; d++) {
            red[warp][d] = aK[d];
            red[warp][8 + d] = aV[d];
        }
    }
    __syncthreads();
    if (tid < 8) {
        kout[i * 8 + tid] = red[0][tid] + red[1][tid] + red[2][tid] + red[3][tid] + bk[tid];
    } else if (tid < 16) {
        int d = tid - 8;
        vout[i * 8 + d] = red[0][tid] + red[1][tid] + red[2][tid] + red[3][tid] + bv[d];
    }
}

// ---------------- Fused causal attention ----------------
// One block per query row i. smem holds K^T [8][1024], V^T [8][1024], q row [2048].
// 8 warps; warp w handles heads w, w+8, ... (32 heads), warp-local reductions only.
__global__ __launch_bounds__(256) void attn_kernel(
    const float* __restrict__ q, const float* __restrict__ kg,
    const float* __restrict__ vg, float* __restrict__ scores,
    float* __restrict__ attn_out, int write_scores)
{
    extern __shared__ float sm[];
    float* ks = sm;                 // [8][S_LEN]
    float* vs = sm + 8 * S_LEN;     // [8][S_LEN]
    float* qs = sm + 16 * S_LEN;    // [DM]

    const int i = blockIdx.x;
    const int tid = threadIdx.x;
    const int nj = i + 1;

    for (int t = tid; t < DM / 4; t += 256)
        ((float4*)qs)[t] = ((const float4*)(q + (size_t)i * DM))[t];

    for (int idx = tid; idx < nj * 2; idx += 256) {
        int j = idx >> 1;
        int h4 = (idx & 1) * 4;
        float4 t = *(const float4*)(kg + j * 8 + h4);
        ks[(h4 + 0) * S_LEN + j] = t.x;
        ks[(h4 + 1) * S_LEN + j] = t.y;
        ks[(h4 + 2) * S_LEN + j] = t.z;
        ks[(h4 + 3) * S_LEN + j] = t.w;
        float4 u = *(const float4*)(vg + j * 8 + h4);
        vs[(h4 + 0) * S_LEN + j] = u.x;
        vs[(h4 + 1) * S_LEN + j] = u.y;
        vs[(h4 + 2) * S_LEN + j] = u.z;
        vs[(h4 + 3) * S_LEN + j] = u.w;
    }
    __syncthreads();

    const int warp = tid >> 5, lane = tid & 31;
    // number of j-chunks this lane participates in: j = lane + 32*c < nj
    const int cmax = (nj - lane + 31) >> 5;   // >= 0

    for (int h = warp; h < NUM_HEADS; h += 8) {
        float qv[8];
#pragma unroll
        for (int d = 0; d < 8; d++) qv[d] = qs[h * 8 + d];

        float e[32];
        float m = -3.0e38f;
#pragma unroll
        for (int c = 0; c < 32; c++) {
            if (c >= cmax) break;
            int j = lane + c * 32;
            float s = qv[0] * ks[j];
#pragma unroll
            for (int d = 1; d < 8; d++) s += qv[d] * ks[d * S_LEN + j];
            s *= ATT_SCALE;
            e[c] = s;
            m = fmaxf(m, s);
        }
#pragma unroll
        for (int o = 16; o > 0; o >>= 1)
            m = fmaxf(m, __shfl_xor_sync(0xffffffffu, m, o));

        float sum = 0.f;
#pragma unroll
        for (int c = 0; c < 32; c++) {
            if (c >= cmax) break;
            float ev = __expf(e[c] - m);
            e[c] = ev;
            sum += ev;
        }
#pragma unroll
        for (int o = 16; o > 0; o >>= 1)
            sum += __shfl_xor_sync(0xffffffffu, sum, o);
        float rinv = 1.0f / sum;

        float ov[8] = {0,0,0,0,0,0,0,0};
        float* srow = scores + ((size_t)h << 20) + ((size_t)i << 10);
#pragma unroll
        for (int c = 0; c < 32; c++) {
            if (c >= cmax) break;
            int j = lane + c * 32;
            float p = e[c] * rinv;
            if (write_scores) srow[j] = p;
#pragma unroll
            for (int d = 0; d < 8; d++) ov[d] += p * vs[d * S_LEN + j];
        }
        if (write_scores) {
            for (int j = nj + lane; j < S_LEN; j += 32) srow[j] = 0.0f;
        }

#pragma unroll
        for (int d = 0; d < 8; d++)
#pragma unroll
            for (int o = 16; o > 0; o >>= 1)
                ov[d] += __shfl_xor_sync(0xffffffffu, ov[d], o);

        if (lane == 0) {
            float* ao = attn_out + (size_t)i * DM + h * 8;
#pragma unroll
            for (int d = 0; d < 8; d++) ao[d] = ov[d];
        }
    }
}

// ---------------- launch ----------------
extern "C" void kernel_launch(void* const* d_in, const int* in_sizes, int n_in,
                              void* d_out, int out_size) {
    const float* x  = (const float*)d_in[0];
    // d_in[1] = mask (int32) — causal, implicit
    const float* Wq = (const float*)d_in[2];
    const float* bq = (const float*)d_in[3];
    const float* Wk = (const float*)d_in[4];
    const float* bk = (const float*)d_in[5];
    const float* Wv = (const float*)d_in[6];
    const float* bv = (const float*)d_in[7];
    const float* Wo = (const float*)d_in[8];
    const float* bo = (const float*)d_in[9];
    float* out = (float*)d_out;

    float *qp, *kp, *vp, *ap;
    cudaGetSymbolAddress((void**)&qp, g_q);
    cudaGetSymbolAddress((void**)&kp, g_k);
    cudaGetSymbolAddress((void**)&vp, g_v);
    cudaGetSymbolAddress((void**)&ap, g_attn);

    const int OUT_ELEMS = S_LEN * DM;                      // 2,097,152
    const long long SCORE_ELEMS = (long long)NUM_HEADS * S_LEN * S_LEN;
    int write_scores = ((long long)out_size >= OUT_ELEMS + SCORE_ELEMS) ? 1 : 0;
    float* scores = out + OUT_ELEMS;

    dim3 g1(DM / BN, S_LEN / BM);
    sgemm_bias<<<g1, 256>>>(x, Wq, bq, qp, S_LEN, DM, DM);
    kv_kernel<<<S_LEN, 128>>>(x, Wk, bk, Wv, bv, kp, vp);

    const int smem_bytes = (16 * S_LEN + DM) * (int)sizeof(float);  // 73728
    cudaFuncSetAttribute(attn_kernel, cudaFuncAttributeMaxDynamicSharedMemorySize, smem_bytes);
    attn_kernel<<<S_LEN, 256, smem_bytes>>>(qp, kp, vp, scores, ap, write_scores);

    sgemm_bias<<<g1, 256>>>(ap, Wo, bo, out, S_LEN, DM, DM);
}